// round 10
// baseline (speedup 1.0000x reference)
#include <cuda_runtime.h>
#include <cuda_bf16.h>
#include <cstdint>

typedef unsigned long long ull;

#define MAXT 66560
#define MAXB 2048

// Scratch (static device allocations — no cudaMalloc allowed)
__device__ float         g_qkv[(size_t)MAXT * 384];
__device__ __nv_bfloat16 g_oh[(size_t)MAXT * 128];
__device__ __nv_bfloat16 g_ol[(size_t)MAXT * 128];
__device__ __nv_bfloat16 g_wh1[384 * 128];
__device__ __nv_bfloat16 g_wl1[384 * 128];
__device__ __nv_bfloat16 g_wh2[128 * 128];
__device__ __nv_bfloat16 g_wl2[128 * 128];
__device__ int           g_offs[MAXB];

// ---------------------------------------------------------------------------
// f32x2 helpers
// ---------------------------------------------------------------------------
__device__ __forceinline__ ull pack2(float lo, float hi) {
    ull r;
    asm("mov.b64 %0, {%1, %2};" : "=l"(r)
        : "r"(__float_as_uint(lo)), "r"(__float_as_uint(hi)));
    return r;
}
__device__ __forceinline__ ull ffma2(ull a, ull b, ull c) {
    ull d;
    asm("fma.rn.f32x2 %0, %1, %2, %3;" : "=l"(d) : "l"(a), "l"(b), "l"(c));
    return d;
}
__device__ __forceinline__ ull mul2(ull a, ull b) {
    ull d;
    asm("mul.rn.f32x2 %0, %1, %2;" : "=l"(d) : "l"(a), "l"(b));
    return d;
}
__device__ __forceinline__ ull add2(ull a, ull b) {
    ull d;
    asm("add.rn.f32x2 %0, %1, %2;" : "=l"(d) : "l"(a), "l"(b));
    return d;
}
__device__ __forceinline__ float lo2(ull v) { return __uint_as_float((unsigned)(v & 0xffffffffull)); }
__device__ __forceinline__ float hi2(ull v) { return __uint_as_float((unsigned)(v >> 32)); }
__device__ __forceinline__ float hadd2(ull v) { return lo2(v) + hi2(v); }

__device__ __forceinline__ uint32_t smem_u32(const void* p) {
    uint32_t a;
    asm("{ .reg .u64 t; cvta.to.shared.u64 t, %1; cvt.u32.u64 %0, t; }" : "=r"(a) : "l"(p));
    return a;
}
__device__ __forceinline__ void cp16(uint32_t s, const void* g) {
    asm volatile("cp.async.ca.shared.global [%0], [%1], 16;" :: "r"(s), "l"(g));
}
#define CP_COMMIT() asm volatile("cp.async.commit_group;" ::: "memory")
#define CP_WAIT()   asm volatile("cp.async.wait_group 0;" ::: "memory")

// ---------------------------------------------------------------------------
// Prep kernel: blocks 0..63 convert weights fp32 -> bf16 hi/lo planes;
// block 64 does the exclusive prefix sum of agents_per_sample.
// ---------------------------------------------------------------------------
__global__ void prep_kernel(const float* __restrict__ w1,
                            const float* __restrict__ w2,
                            const int* __restrict__ agents, int B)
{
    int bid = blockIdx.x;
    int tid = threadIdx.x;

    if (bid == 64) {
        // ---- scan ----
        __shared__ int part[256];
        int local[8];
        int s = 0;
#pragma unroll
        for (int i = 0; i < 8; i++) {
            int idx = tid * 8 + i;
            local[i] = (idx < B) ? agents[idx] : 0;
            s += local[i];
        }
        part[tid] = s;
        __syncthreads();
        for (int d = 1; d < 256; d <<= 1) {
            int v = (tid >= d) ? part[tid - d] : 0;
            __syncthreads();
            part[tid] += v;
            __syncthreads();
        }
        int base = (tid > 0) ? part[tid - 1] : 0;
#pragma unroll
        for (int i = 0; i < 8; i++) {
            int idx = tid * 8 + i;
            if (idx < B) g_offs[idx] = base;
            base += local[i];
        }
        return;
    }

    // ---- weight conversion ----
    const float* src;
    __nv_bfloat16 *dh, *dl;
    int i;
    if (bid < 48) {
        src = w1; dh = g_wh1; dl = g_wl1;
        i = bid * 256 + tid;                  // < 12288 float4s
    } else {
        src = w2; dh = g_wh2; dl = g_wl2;
        i = (bid - 48) * 256 + tid;           // < 4096 float4s
    }
    float4 v = ((const float4*)src)[i];
    __nv_bfloat16 hx = __float2bfloat16(v.x), hy = __float2bfloat16(v.y),
                  hz = __float2bfloat16(v.z), hw = __float2bfloat16(v.w);
    ull hp = (ull)__bfloat16_as_ushort(hx) | ((ull)__bfloat16_as_ushort(hy) << 16)
           | ((ull)__bfloat16_as_ushort(hz) << 32) | ((ull)__bfloat16_as_ushort(hw) << 48);
    __nv_bfloat16 lx = __float2bfloat16(v.x - __bfloat162float(hx));
    __nv_bfloat16 ly = __float2bfloat16(v.y - __bfloat162float(hy));
    __nv_bfloat16 lz = __float2bfloat16(v.z - __bfloat162float(hz));
    __nv_bfloat16 lw = __float2bfloat16(v.w - __bfloat162float(hw));
    ull lp = (ull)__bfloat16_as_ushort(lx) | ((ull)__bfloat16_as_ushort(ly) << 16)
           | ((ull)__bfloat16_as_ushort(lz) << 32) | ((ull)__bfloat16_as_ushort(lw) << 48);
    *(ull*)(dh + (size_t)i * 4) = hp;
    *(ull*)(dl + (size_t)i * 4) = lp;
}

// ---------------------------------------------------------------------------
// GEMM (warp HMMA): 64x128 CTA tile, K=128, 2 CTAs/SM.
// CONVERT_A: A read as fp32 and split in-kernel; else A read as bf16 planes.
// W always pre-converted planes via cp.async. B frags via ldmatrix.x4.
// 3-term split: Ah*Wh + Ah*Wl + Al*Wh.
// ---------------------------------------------------------------------------
#define ASTRIDE 136                  // bf16 elems per smem row (272B)
#define SA_H 0
#define SA_L 17408                   // 64*136*2
#define SW_H 34816
#define SW_L 69632
#define GEMM_SMEM 104448

__device__ __forceinline__ void ldm_x4(uint32_t* r, uint32_t addr) {
    asm volatile("ldmatrix.sync.aligned.m8n8.x4.shared.b16 {%0,%1,%2,%3}, [%4];"
                 : "=r"(r[0]), "=r"(r[1]), "=r"(r[2]), "=r"(r[3]) : "r"(addr));
}
__device__ __forceinline__ void mma_bf16(float* d, const uint32_t* a, const uint32_t* b) {
    asm volatile("mma.sync.aligned.m16n8k16.row.col.f32.bf16.bf16.f32 "
                 "{%0,%1,%2,%3}, {%4,%5,%6,%7}, {%8,%9}, {%0,%1,%2,%3};"
                 : "+f"(d[0]), "+f"(d[1]), "+f"(d[2]), "+f"(d[3])
                 : "r"(a[0]), "r"(a[1]), "r"(a[2]), "r"(a[3]), "r"(b[0]), "r"(b[1]));
}

template <bool CONVERT_A>
__global__ __launch_bounds__(256, 2) void gemm_tc_kernel(
    const void* __restrict__ Asrc,                 // fp32 [.][128] or unused
    const __nv_bfloat16* __restrict__ Ah_g, const __nv_bfloat16* __restrict__ Al_g,
    const __nv_bfloat16* __restrict__ Wh, const __nv_bfloat16* __restrict__ Wl,
    const float* __restrict__ bias, float* __restrict__ C, int N)
{
    extern __shared__ char sm[];
    const uint32_t sb = smem_u32(sm);
    const int tid  = threadIdx.x;
    const int wid  = tid >> 5;
    const int lane = tid & 31;
    const int bm   = blockIdx.x * 64;
    const int bn   = blockIdx.y * 128;

    // ---- W planes via cp.async (128 rows) ----
#pragma unroll
    for (int t = 0; t < 8; t++) {
        int c = tid + t * 256;           // 0..2047
        int row = c >> 4, c16 = c & 15;
        uint32_t so = (uint32_t)(row * 272 + c16 * 16);
        cp16(sb + SW_H + so, (const char*)(Wh + (size_t)(bn + row) * 128) + c16 * 16);
        cp16(sb + SW_L + so, (const char*)(Wl + (size_t)(bn + row) * 128) + c16 * 16);
    }

    // ---- A tile (64 rows) ----
    if (CONVERT_A) {
        const float* A = (const float*)Asrc;
#pragma unroll
        for (int it = 0; it < 8; it++) {
            int idx = tid + it * 256;            // 0..2047 float4s
            int row = idx >> 5;
            int col = (idx & 31) * 4;
            int so  = row * ASTRIDE + col;
            float4 v = *(const float4*)(A + (size_t)(bm + row) * 128 + col);
            __nv_bfloat16 hx = __float2bfloat16(v.x), hy = __float2bfloat16(v.y),
                          hz = __float2bfloat16(v.z), hw = __float2bfloat16(v.w);
            ull hp = (ull)__bfloat16_as_ushort(hx) | ((ull)__bfloat16_as_ushort(hy) << 16)
                   | ((ull)__bfloat16_as_ushort(hz) << 32) | ((ull)__bfloat16_as_ushort(hw) << 48);
            __nv_bfloat16 lx = __float2bfloat16(v.x - __bfloat162float(hx));
            __nv_bfloat16 ly = __float2bfloat16(v.y - __bfloat162float(hy));
            __nv_bfloat16 lz = __float2bfloat16(v.z - __bfloat162float(hz));
            __nv_bfloat16 lw = __float2bfloat16(v.w - __bfloat162float(hw));
            ull lp = (ull)__bfloat16_as_ushort(lx) | ((ull)__bfloat16_as_ushort(ly) << 16)
                   | ((ull)__bfloat16_as_ushort(lz) << 32) | ((ull)__bfloat16_as_ushort(lw) << 48);
            *(ull*)(sm + SA_H + so * 2) = hp;
            *(ull*)(sm + SA_L + so * 2) = lp;
        }
    } else {
#pragma unroll
        for (int t = 0; t < 4; t++) {
            int c = tid + t * 256;           // 0..1023
            int row = c >> 4, c16 = c & 15;
            uint32_t so = (uint32_t)(row * 272 + c16 * 16);
            cp16(sb + SA_H + so, (const char*)(Ah_g + (size_t)(bm + row) * 128) + c16 * 16);
            cp16(sb + SA_L + so, (const char*)(Al_g + (size_t)(bm + row) * 128) + c16 * 16);
        }
    }
    CP_COMMIT();
    CP_WAIT();
    __syncthreads();

    // ---- mainloop: 8 warps in 2(m) x 4(n); warp region 32x32 ----
    const int wm = (wid & 1) * 32;
    const int wn = (wid >> 1) * 32;

    float acc[2][4][4];
#pragma unroll
    for (int mi = 0; mi < 2; mi++)
#pragma unroll
        for (int ni = 0; ni < 4; ni++)
#pragma unroll
            for (int e = 0; e < 4; e++) acc[mi][ni][e] = 0.f;

    const int arow = wm + (lane & 15);
    const int bgrp = lane >> 3;
    const int brow0 = wn + ((bgrp >> 1) << 3) + (lane & 7);
    const int bk8   = (bgrp & 1) << 3;

#pragma unroll
    for (int k = 0; k < 8; k++) {
        const int kb = k * 16;
        uint32_t ahf[2][4], alf[2][4];
#pragma unroll
        for (int mi = 0; mi < 2; mi++) {
            uint32_t off = (uint32_t)(((arow + mi * 16) * ASTRIDE + kb + (lane >> 4) * 8) * 2);
            ldm_x4(ahf[mi], sb + SA_H + off);
            ldm_x4(alf[mi], sb + SA_L + off);
        }
        uint32_t bhf[4][2], blf[4][2];
#pragma unroll
        for (int nip = 0; nip < 2; nip++) {
            uint32_t off = (uint32_t)(((brow0 + nip * 16) * ASTRIDE + kb + bk8) * 2);
            ldm_x4(&bhf[nip * 2][0], sb + SW_H + off);
            ldm_x4(&blf[nip * 2][0], sb + SW_L + off);
        }
#pragma unroll
        for (int mi = 0; mi < 2; mi++)
#pragma unroll
            for (int ni = 0; ni < 4; ni++) {
                mma_bf16(acc[mi][ni], ahf[mi], bhf[ni]);
                mma_bf16(acc[mi][ni], ahf[mi], blf[ni]);
                mma_bf16(acc[mi][ni], alf[mi], bhf[ni]);
            }
    }

    // ---- epilogue: bias + store ----
    const int er = lane >> 2;
    const int ec = (lane & 3) * 2;
#pragma unroll
    for (int ni = 0; ni < 4; ni++) {
        int n = bn + wn + ni * 8 + ec;
        float b0 = bias[n], b1 = bias[n + 1];
#pragma unroll
        for (int mi = 0; mi < 2; mi++) {
            int m0 = bm + wm + mi * 16 + er;
            *(float2*)(C + (size_t)m0 * N + n) =
                make_float2(acc[mi][ni][0] + b0, acc[mi][ni][1] + b1);
            *(float2*)(C + (size_t)(m0 + 8) * N + n) =
                make_float2(acc[mi][ni][2] + b0, acc[mi][ni][3] + b1);
        }
    }
}

// ---------------------------------------------------------------------------
// Attention v5: block per (sample, query-half), warp per head, lane per query.
// Single-query path everywhere -> ~70 regs -> 3 CTAs/SM. Half-1 blocks exit
// immediately when n <= 32. Largest-n samples scheduled first.
// Writes bf16 hi/lo output planes (fuses out_proj input conversion).
// ---------------------------------------------------------------------------
__device__ __forceinline__ void store_bf_split(
    __nv_bfloat16* __restrict__ Oh, __nv_bfloat16* __restrict__ Ol,
    size_t base, const ull* ov, float linv)
{
    ull inv = pack2(linv, linv);
#pragma unroll
    for (int t = 0; t < 4; t++) {
        ull r0 = mul2(ov[2 * t], inv);
        ull r1 = mul2(ov[2 * t + 1], inv);
        float f0 = lo2(r0), f1 = hi2(r0), f2 = lo2(r1), f3 = hi2(r1);
        __nv_bfloat16 h0 = __float2bfloat16(f0), h1 = __float2bfloat16(f1),
                      h2 = __float2bfloat16(f2), h3 = __float2bfloat16(f3);
        ull hp = (ull)__bfloat16_as_ushort(h0) | ((ull)__bfloat16_as_ushort(h1) << 16)
               | ((ull)__bfloat16_as_ushort(h2) << 32) | ((ull)__bfloat16_as_ushort(h3) << 48);
        __nv_bfloat16 l0 = __float2bfloat16(f0 - __bfloat162float(h0));
        __nv_bfloat16 l1 = __float2bfloat16(f1 - __bfloat162float(h1));
        __nv_bfloat16 l2 = __float2bfloat16(f2 - __bfloat162float(h2));
        __nv_bfloat16 l3 = __float2bfloat16(f3 - __bfloat162float(h3));
        ull lp = (ull)__bfloat16_as_ushort(l0) | ((ull)__bfloat16_as_ushort(l1) << 16)
               | ((ull)__bfloat16_as_ushort(l2) << 32) | ((ull)__bfloat16_as_ushort(l3) << 48);
        *(ull*)(Oh + base + t * 4) = hp;
        *(ull*)(Ol + base + t * 4) = lp;
    }
}

__global__ __launch_bounds__(256) void attn_kernel(
    const float* __restrict__ Y,            // qkv [T][384]
    __nv_bfloat16* __restrict__ Oh,         // attn out hi plane [T][128]
    __nv_bfloat16* __restrict__ Ol,         // attn out lo plane [T][128]
    const int* __restrict__ agents, int B)
{
    extern __shared__ float smf[];       // 8 warps * (1024 K + 1024 V) floats
    // largest-first schedule (heuristic permutation; correctness reads agents[])
    int b = blockIdx.x;
    if (B == 2048) {
        int g = b >> 5, k = b & 31;
        b = (k << 6) + (63 - g);
    }
    const int half = blockIdx.y;
    const int n    = agents[b];
    if (half && n <= 32) return;         // uniform early exit, before any barrier

    const int o    = g_offs[b];
    const int tid  = threadIdx.x;
    const int w    = tid >> 5;           // head index
    const int lane = tid & 31;

    float* Ks = smf + w * 2048;
    float* Vs = Ks + 1024;

    // fill K/V for this head (own warp only -> __syncwarp suffices)
    int nseg = n * 4;
    for (int si = lane; si < nseg; si += 32) {
        int r = si >> 2, s = si & 3;
        const float* base = Y + (size_t)(o + r) * 384 + w * 16 + s * 4;
        *(float4*)(Ks + r * 16 + s * 4) = *(const float4*)(base + 128);
        *(float4*)(Vs + r * 16 + s * 4) = *(const float4*)(base + 256);
    }
    __syncwarp();

    const int i0 = half * 32 + lane;
    const bool valid = i0 < n;
    const ull QSC = pack2(0.25f, 0.25f);

    ull q0[8];
#pragma unroll
    for (int d = 0; d < 8; d++) q0[d] = 0ull;
    if (valid) {
        const float4* qp = (const float4*)(Y + (size_t)(o + i0) * 384 + w * 16);
#pragma unroll
        for (int t = 0; t < 4; t++) {
            float4 v = qp[t];
            q0[t * 2 + 0] = mul2(pack2(v.x, v.y), QSC);
            q0[t * 2 + 1] = mul2(pack2(v.z, v.w), QSC);
        }
    }

    ull o0[8];
#pragma unroll
    for (int d = 0; d < 8; d++) o0[d] = 0ull;
    float l0 = 0.f;

#pragma unroll 2
    for (int j = 0; j < n; j++) {
        const ulonglong2* kp = (const ulonglong2*)(Ks + j * 16);
        ulonglong2 k01 = kp[0], k23 = kp[1], k45 = kp[2], k67 = kp[3];

        ull saA = 0, saB = 0;
        saA = ffma2(q0[0], k01.x, saA);
        saB = ffma2(q0[1], k01.y, saB);
        saA = ffma2(q0[2], k23.x, saA);
        saB = ffma2(q0[3], k23.y, saB);
        saA = ffma2(q0[4], k45.x, saA);
        saB = ffma2(q0[5], k45.y, saB);
        saA = ffma2(q0[6], k67.x, saA);
        saB = ffma2(q0[7], k67.y, saB);

        float e0 = __expf(hadd2(add2(saA, saB)));
        l0 += e0;
        ull e00 = pack2(e0, e0);

        const ulonglong2* vp = (const ulonglong2*)(Vs + j * 16);
        ulonglong2 v01 = vp[0], v23 = vp[1], v45 = vp[2], v67 = vp[3];
        o0[0] = ffma2(e00, v01.x, o0[0]);
        o0[1] = ffma2(e00, v01.y, o0[1]);
        o0[2] = ffma2(e00, v23.x, o0[2]);
        o0[3] = ffma2(e00, v23.y, o0[3]);
        o0[4] = ffma2(e00, v45.x, o0[4]);
        o0[5] = ffma2(e00, v45.y, o0[5]);
        o0[6] = ffma2(e00, v67.x, o0[6]);
        o0[7] = ffma2(e00, v67.y, o0[7]);
    }

    if (valid)
        store_bf_split(Oh, Ol, (size_t)(o + i0) * 128 + w * 16, o0, 1.f / l0);
}

// ---------------------------------------------------------------------------
extern "C" void kernel_launch(void* const* d_in, const int* in_sizes, int n_in,
                              void* d_out, int out_size)
{
    const float* att_in = (const float*)d_in[0];
    const float* in_w   = (const float*)d_in[1];
    const float* in_b   = (const float*)d_in[2];
    const float* out_w  = (const float*)d_in[3];
    const float* out_b  = (const float*)d_in[4];
    const int*   agents = (const int*)d_in[5];

    const int T = in_sizes[0] / 128;
    const int B = in_sizes[5];
    float* out  = (float*)d_out;

    float *qkv = nullptr;
    __nv_bfloat16 *oh, *ol, *wh1, *wl1, *wh2, *wl2;
    cudaGetSymbolAddress((void**)&qkv, g_qkv);
    cudaGetSymbolAddress((void**)&oh,  g_oh);
    cudaGetSymbolAddress((void**)&ol,  g_ol);
    cudaGetSymbolAddress((void**)&wh1, g_wh1);
    cudaGetSymbolAddress((void**)&wl1, g_wl1);
    cudaGetSymbolAddress((void**)&wh2, g_wh2);
    cudaGetSymbolAddress((void**)&wl2, g_wl2);

    cudaFuncSetAttribute(gemm_tc_kernel<true>,  cudaFuncAttributeMaxDynamicSharedMemorySize, GEMM_SMEM);
    cudaFuncSetAttribute(gemm_tc_kernel<false>, cudaFuncAttributeMaxDynamicSharedMemorySize, GEMM_SMEM);
    cudaFuncSetAttribute(attn_kernel, cudaFuncAttributeMaxDynamicSharedMemorySize, 65536);

    prep_kernel<<<65, 256>>>(in_w, out_w, agents, B);

    // QKV GEMM: [T x 384], A converted in-kernel
    dim3 g1(T / 64, 3);
    gemm_tc_kernel<true><<<g1, 256, GEMM_SMEM>>>(att_in, nullptr, nullptr,
                                                 wh1, wl1, in_b, qkv, 384);

    // attention -> bf16 hi/lo planes
    dim3 ga(B, 2);
    attn_kernel<<<ga, 256, 65536>>>(qkv, oh, ol, agents, B);

    // out_proj GEMM: [T x 128], A = preconverted planes
    dim3 g2(T / 64, 1);
    gemm_tc_kernel<false><<<g2, 256, GEMM_SMEM>>>(nullptr, oh, ol,
                                                  wh2, wl2, out_b, out, 128);
}

// round 11
// speedup vs baseline: 1.1002x; 1.1002x over previous
#include <cuda_runtime.h>
#include <cuda_bf16.h>
#include <cstdint>

typedef unsigned long long ull;

#define MAXT 66560
#define MAXB 2048

// Scratch (static device allocations — no cudaMalloc allowed)
__device__ float         g_qkv[(size_t)MAXT * 384];
__device__ __nv_bfloat16 g_oh[(size_t)MAXT * 128];
__device__ __nv_bfloat16 g_ol[(size_t)MAXT * 128];
__device__ __nv_bfloat16 g_wh1[384 * 128];
__device__ __nv_bfloat16 g_wl1[384 * 128];
__device__ __nv_bfloat16 g_wh2[128 * 128];
__device__ __nv_bfloat16 g_wl2[128 * 128];
__device__ int           g_offs[MAXB];

// ---------------------------------------------------------------------------
// f32x2 helpers
// ---------------------------------------------------------------------------
__device__ __forceinline__ ull pack2(float lo, float hi) {
    ull r;
    asm("mov.b64 %0, {%1, %2};" : "=l"(r)
        : "r"(__float_as_uint(lo)), "r"(__float_as_uint(hi)));
    return r;
}
__device__ __forceinline__ ull ffma2(ull a, ull b, ull c) {
    ull d;
    asm("fma.rn.f32x2 %0, %1, %2, %3;" : "=l"(d) : "l"(a), "l"(b), "l"(c));
    return d;
}
__device__ __forceinline__ ull mul2(ull a, ull b) {
    ull d;
    asm("mul.rn.f32x2 %0, %1, %2;" : "=l"(d) : "l"(a), "l"(b));
    return d;
}
__device__ __forceinline__ ull add2(ull a, ull b) {
    ull d;
    asm("add.rn.f32x2 %0, %1, %2;" : "=l"(d) : "l"(a), "l"(b));
    return d;
}
__device__ __forceinline__ float lo2(ull v) { return __uint_as_float((unsigned)(v & 0xffffffffull)); }
__device__ __forceinline__ float hi2(ull v) { return __uint_as_float((unsigned)(v >> 32)); }
__device__ __forceinline__ float hadd2(ull v) { return lo2(v) + hi2(v); }

__device__ __forceinline__ uint32_t smem_u32(const void* p) {
    uint32_t a;
    asm("{ .reg .u64 t; cvta.to.shared.u64 t, %1; cvt.u32.u64 %0, t; }" : "=r"(a) : "l"(p));
    return a;
}
__device__ __forceinline__ void cp16(uint32_t s, const void* g) {
    asm volatile("cp.async.ca.shared.global [%0], [%1], 16;" :: "r"(s), "l"(g));
}
#define CP_COMMIT() asm volatile("cp.async.commit_group;" ::: "memory")
#define CP_WAIT()   asm volatile("cp.async.wait_group 0;" ::: "memory")

// ---------------------------------------------------------------------------
// Prep kernel: blocks 0..63 convert weights fp32 -> bf16 hi/lo planes;
// block 64 does the exclusive prefix sum of agents_per_sample.
// ---------------------------------------------------------------------------
__global__ void prep_kernel(const float* __restrict__ w1,
                            const float* __restrict__ w2,
                            const int* __restrict__ agents, int B)
{
    int bid = blockIdx.x;
    int tid = threadIdx.x;

    if (bid == 64) {
        // ---- scan ----
        __shared__ int part[256];
        int local[8];
        int s = 0;
#pragma unroll
        for (int i = 0; i < 8; i++) {
            int idx = tid * 8 + i;
            local[i] = (idx < B) ? agents[idx] : 0;
            s += local[i];
        }
        part[tid] = s;
        __syncthreads();
        for (int d = 1; d < 256; d <<= 1) {
            int v = (tid >= d) ? part[tid - d] : 0;
            __syncthreads();
            part[tid] += v;
            __syncthreads();
        }
        int base = (tid > 0) ? part[tid - 1] : 0;
#pragma unroll
        for (int i = 0; i < 8; i++) {
            int idx = tid * 8 + i;
            if (idx < B) g_offs[idx] = base;
            base += local[i];
        }
        return;
    }

    // ---- weight conversion ----
    const float* src;
    __nv_bfloat16 *dh, *dl;
    int i;
    if (bid < 48) {
        src = w1; dh = g_wh1; dl = g_wl1;
        i = bid * 256 + tid;                  // < 12288 float4s
    } else {
        src = w2; dh = g_wh2; dl = g_wl2;
        i = (bid - 48) * 256 + tid;           // < 4096 float4s
    }
    float4 v = ((const float4*)src)[i];
    __nv_bfloat16 hx = __float2bfloat16(v.x), hy = __float2bfloat16(v.y),
                  hz = __float2bfloat16(v.z), hw = __float2bfloat16(v.w);
    ull hp = (ull)__bfloat16_as_ushort(hx) | ((ull)__bfloat16_as_ushort(hy) << 16)
           | ((ull)__bfloat16_as_ushort(hz) << 32) | ((ull)__bfloat16_as_ushort(hw) << 48);
    __nv_bfloat16 lx = __float2bfloat16(v.x - __bfloat162float(hx));
    __nv_bfloat16 ly = __float2bfloat16(v.y - __bfloat162float(hy));
    __nv_bfloat16 lz = __float2bfloat16(v.z - __bfloat162float(hz));
    __nv_bfloat16 lw = __float2bfloat16(v.w - __bfloat162float(hw));
    ull lp = (ull)__bfloat16_as_ushort(lx) | ((ull)__bfloat16_as_ushort(ly) << 16)
           | ((ull)__bfloat16_as_ushort(lz) << 32) | ((ull)__bfloat16_as_ushort(lw) << 48);
    *(ull*)(dh + (size_t)i * 4) = hp;
    *(ull*)(dl + (size_t)i * 4) = lp;
}

// ---------------------------------------------------------------------------
// GEMM (warp HMMA): 64x128 CTA tile, K=128, 2 CTAs/SM.
// CONVERT_A: A read as fp32 and split in-kernel; else A read as bf16 planes.
// W always pre-converted planes via cp.async. B frags via ldmatrix.x4.
// 3-term split: Ah*Wh + Ah*Wl + Al*Wh.
// ---------------------------------------------------------------------------
#define ASTRIDE 136                  // bf16 elems per smem row (272B)
#define SA_H 0
#define SA_L 17408                   // 64*136*2
#define SW_H 34816
#define SW_L 69632
#define GEMM_SMEM 104448

__device__ __forceinline__ void ldm_x4(uint32_t* r, uint32_t addr) {
    asm volatile("ldmatrix.sync.aligned.m8n8.x4.shared.b16 {%0,%1,%2,%3}, [%4];"
                 : "=r"(r[0]), "=r"(r[1]), "=r"(r[2]), "=r"(r[3]) : "r"(addr));
}
__device__ __forceinline__ void mma_bf16(float* d, const uint32_t* a, const uint32_t* b) {
    asm volatile("mma.sync.aligned.m16n8k16.row.col.f32.bf16.bf16.f32 "
                 "{%0,%1,%2,%3}, {%4,%5,%6,%7}, {%8,%9}, {%0,%1,%2,%3};"
                 : "+f"(d[0]), "+f"(d[1]), "+f"(d[2]), "+f"(d[3])
                 : "r"(a[0]), "r"(a[1]), "r"(a[2]), "r"(a[3]), "r"(b[0]), "r"(b[1]));
}

template <bool CONVERT_A>
__global__ __launch_bounds__(256, 2) void gemm_tc_kernel(
    const void* __restrict__ Asrc,                 // fp32 [.][128] or unused
    const __nv_bfloat16* __restrict__ Ah_g, const __nv_bfloat16* __restrict__ Al_g,
    const __nv_bfloat16* __restrict__ Wh, const __nv_bfloat16* __restrict__ Wl,
    const float* __restrict__ bias, float* __restrict__ C, int N)
{
    extern __shared__ char sm[];
    const uint32_t sb = smem_u32(sm);
    const int tid  = threadIdx.x;
    const int wid  = tid >> 5;
    const int lane = tid & 31;
    const int bm   = blockIdx.x * 64;
    const int bn   = blockIdx.y * 128;

    // ---- W planes via cp.async (128 rows) ----
#pragma unroll
    for (int t = 0; t < 8; t++) {
        int c = tid + t * 256;           // 0..2047
        int row = c >> 4, c16 = c & 15;
        uint32_t so = (uint32_t)(row * 272 + c16 * 16);
        cp16(sb + SW_H + so, (const char*)(Wh + (size_t)(bn + row) * 128) + c16 * 16);
        cp16(sb + SW_L + so, (const char*)(Wl + (size_t)(bn + row) * 128) + c16 * 16);
    }

    // ---- A tile (64 rows) ----
    if (CONVERT_A) {
        const float* A = (const float*)Asrc;
#pragma unroll
        for (int it = 0; it < 8; it++) {
            int idx = tid + it * 256;            // 0..2047 float4s
            int row = idx >> 5;
            int col = (idx & 31) * 4;
            int so  = row * ASTRIDE + col;
            float4 v = *(const float4*)(A + (size_t)(bm + row) * 128 + col);
            __nv_bfloat16 hx = __float2bfloat16(v.x), hy = __float2bfloat16(v.y),
                          hz = __float2bfloat16(v.z), hw = __float2bfloat16(v.w);
            ull hp = (ull)__bfloat16_as_ushort(hx) | ((ull)__bfloat16_as_ushort(hy) << 16)
                   | ((ull)__bfloat16_as_ushort(hz) << 32) | ((ull)__bfloat16_as_ushort(hw) << 48);
            __nv_bfloat16 lx = __float2bfloat16(v.x - __bfloat162float(hx));
            __nv_bfloat16 ly = __float2bfloat16(v.y - __bfloat162float(hy));
            __nv_bfloat16 lz = __float2bfloat16(v.z - __bfloat162float(hz));
            __nv_bfloat16 lw = __float2bfloat16(v.w - __bfloat162float(hw));
            ull lp = (ull)__bfloat16_as_ushort(lx) | ((ull)__bfloat16_as_ushort(ly) << 16)
                   | ((ull)__bfloat16_as_ushort(lz) << 32) | ((ull)__bfloat16_as_ushort(lw) << 48);
            *(ull*)(sm + SA_H + so * 2) = hp;
            *(ull*)(sm + SA_L + so * 2) = lp;
        }
    } else {
#pragma unroll
        for (int t = 0; t < 4; t++) {
            int c = tid + t * 256;           // 0..1023
            int row = c >> 4, c16 = c & 15;
            uint32_t so = (uint32_t)(row * 272 + c16 * 16);
            cp16(sb + SA_H + so, (const char*)(Ah_g + (size_t)(bm + row) * 128) + c16 * 16);
            cp16(sb + SA_L + so, (const char*)(Al_g + (size_t)(bm + row) * 128) + c16 * 16);
        }
    }
    CP_COMMIT();
    CP_WAIT();
    __syncthreads();

    // ---- mainloop: 8 warps in 2(m) x 4(n); warp region 32x32 ----
    const int wm = (wid & 1) * 32;
    const int wn = (wid >> 1) * 32;

    float acc[2][4][4];
#pragma unroll
    for (int mi = 0; mi < 2; mi++)
#pragma unroll
        for (int ni = 0; ni < 4; ni++)
#pragma unroll
            for (int e = 0; e < 4; e++) acc[mi][ni][e] = 0.f;

    const int arow = wm + (lane & 15);
    const int bgrp = lane >> 3;
    const int brow0 = wn + ((bgrp >> 1) << 3) + (lane & 7);
    const int bk8   = (bgrp & 1) << 3;

#pragma unroll
    for (int k = 0; k < 8; k++) {
        const int kb = k * 16;
        uint32_t ahf[2][4], alf[2][4];
#pragma unroll
        for (int mi = 0; mi < 2; mi++) {
            uint32_t off = (uint32_t)(((arow + mi * 16) * ASTRIDE + kb + (lane >> 4) * 8) * 2);
            ldm_x4(ahf[mi], sb + SA_H + off);
            ldm_x4(alf[mi], sb + SA_L + off);
        }
        uint32_t bhf[4][2], blf[4][2];
#pragma unroll
        for (int nip = 0; nip < 2; nip++) {
            uint32_t off = (uint32_t)(((brow0 + nip * 16) * ASTRIDE + kb + bk8) * 2);
            ldm_x4(&bhf[nip * 2][0], sb + SW_H + off);
            ldm_x4(&blf[nip * 2][0], sb + SW_L + off);
        }
#pragma unroll
        for (int mi = 0; mi < 2; mi++)
#pragma unroll
            for (int ni = 0; ni < 4; ni++) {
                mma_bf16(acc[mi][ni], ahf[mi], bhf[ni]);
                mma_bf16(acc[mi][ni], ahf[mi], blf[ni]);
                mma_bf16(acc[mi][ni], alf[mi], bhf[ni]);
            }
    }

    // ---- epilogue: bias + store ----
    const int er = lane >> 2;
    const int ec = (lane & 3) * 2;
#pragma unroll
    for (int ni = 0; ni < 4; ni++) {
        int n = bn + wn + ni * 8 + ec;
        float b0 = bias[n], b1 = bias[n + 1];
#pragma unroll
        for (int mi = 0; mi < 2; mi++) {
            int m0 = bm + wm + mi * 16 + er;
            *(float2*)(C + (size_t)m0 * N + n) =
                make_float2(acc[mi][ni][0] + b0, acc[mi][ni][1] + b1);
            *(float2*)(C + (size_t)(m0 + 8) * N + n) =
                make_float2(acc[mi][ni][2] + b0, acc[mi][ni][3] + b1);
        }
    }
}

// ---------------------------------------------------------------------------
// Attention v6: block per sample, warp per head (fill K/V ONCE, __syncwarp
// only), query halves processed SEQUENTIALLY by the same warp -> single-query
// register footprint (~70 regs) -> 3 CTAs/SM via __launch_bounds__(256,3).
// Writes bf16 hi/lo output planes (fuses out_proj input conversion).
// ---------------------------------------------------------------------------
__device__ __forceinline__ void store_bf_split(
    __nv_bfloat16* __restrict__ Oh, __nv_bfloat16* __restrict__ Ol,
    size_t base, const ull* ov, float linv)
{
    ull inv = pack2(linv, linv);
#pragma unroll
    for (int t = 0; t < 4; t++) {
        ull r0 = mul2(ov[2 * t], inv);
        ull r1 = mul2(ov[2 * t + 1], inv);
        float f0 = lo2(r0), f1 = hi2(r0), f2 = lo2(r1), f3 = hi2(r1);
        __nv_bfloat16 h0 = __float2bfloat16(f0), h1 = __float2bfloat16(f1),
                      h2 = __float2bfloat16(f2), h3 = __float2bfloat16(f3);
        ull hp = (ull)__bfloat16_as_ushort(h0) | ((ull)__bfloat16_as_ushort(h1) << 16)
               | ((ull)__bfloat16_as_ushort(h2) << 32) | ((ull)__bfloat16_as_ushort(h3) << 48);
        __nv_bfloat16 l0 = __float2bfloat16(f0 - __bfloat162float(h0));
        __nv_bfloat16 l1 = __float2bfloat16(f1 - __bfloat162float(h1));
        __nv_bfloat16 l2 = __float2bfloat16(f2 - __bfloat162float(h2));
        __nv_bfloat16 l3 = __float2bfloat16(f3 - __bfloat162float(h3));
        ull lp = (ull)__bfloat16_as_ushort(l0) | ((ull)__bfloat16_as_ushort(l1) << 16)
               | ((ull)__bfloat16_as_ushort(l2) << 32) | ((ull)__bfloat16_as_ushort(l3) << 48);
        *(ull*)(Oh + base + t * 4) = hp;
        *(ull*)(Ol + base + t * 4) = lp;
    }
}

__global__ __launch_bounds__(256, 3) void attn_kernel(
    const float* __restrict__ Y,            // qkv [T][384]
    __nv_bfloat16* __restrict__ Oh,         // attn out hi plane [T][128]
    __nv_bfloat16* __restrict__ Ol,         // attn out lo plane [T][128]
    const int* __restrict__ agents, int B)
{
    extern __shared__ float smf[];       // 8 warps * (1024 K + 1024 V) floats
    // largest-first schedule (heuristic permutation; correctness reads agents[])
    int b = blockIdx.x;
    if (B == 2048) {
        int g = b >> 5, k = b & 31;
        b = (k << 6) + (63 - g);
    }
    const int n    = agents[b];
    const int o    = g_offs[b];
    const int tid  = threadIdx.x;
    const int w    = tid >> 5;           // head index
    const int lane = tid & 31;

    float* Ks = smf + w * 2048;
    float* Vs = Ks + 1024;

    // fill K/V for this head ONCE (own warp reads only its own head)
    int nseg = n * 4;
    for (int si = lane; si < nseg; si += 32) {
        int r = si >> 2, s = si & 3;
        const float* base = Y + (size_t)(o + r) * 384 + w * 16 + s * 4;
        *(float4*)(Ks + r * 16 + s * 4) = *(const float4*)(base + 128);
        *(float4*)(Vs + r * 16 + s * 4) = *(const float4*)(base + 256);
    }
    __syncwarp();

    const ull QSC = pack2(0.25f, 0.25f);
    const int nhalves = (n > 32) ? 2 : 1;

    for (int half = 0; half < nhalves; half++) {
        const int i0 = half * 32 + lane;
        const bool valid = i0 < n;

        ull q0[8];
#pragma unroll
        for (int d = 0; d < 8; d++) q0[d] = 0ull;
        if (valid) {
            const float4* qp = (const float4*)(Y + (size_t)(o + i0) * 384 + w * 16);
#pragma unroll
            for (int t = 0; t < 4; t++) {
                float4 v = qp[t];
                q0[t * 2 + 0] = mul2(pack2(v.x, v.y), QSC);
                q0[t * 2 + 1] = mul2(pack2(v.z, v.w), QSC);
            }
        }

        ull o0[8];
#pragma unroll
        for (int d = 0; d < 8; d++) o0[d] = 0ull;
        float l0 = 0.f;

#pragma unroll 2
        for (int j = 0; j < n; j++) {
            const ulonglong2* kp = (const ulonglong2*)(Ks + j * 16);
            ulonglong2 k01 = kp[0], k23 = kp[1], k45 = kp[2], k67 = kp[3];

            ull saA = 0, saB = 0;
            saA = ffma2(q0[0], k01.x, saA);
            saB = ffma2(q0[1], k01.y, saB);
            saA = ffma2(q0[2], k23.x, saA);
            saB = ffma2(q0[3], k23.y, saB);
            saA = ffma2(q0[4], k45.x, saA);
            saB = ffma2(q0[5], k45.y, saB);
            saA = ffma2(q0[6], k67.x, saA);
            saB = ffma2(q0[7], k67.y, saB);

            float e0 = __expf(hadd2(add2(saA, saB)));
            l0 += e0;
            ull e00 = pack2(e0, e0);

            const ulonglong2* vp = (const ulonglong2*)(Vs + j * 16);
            ulonglong2 v01 = vp[0], v23 = vp[1], v45 = vp[2], v67 = vp[3];
            o0[0] = ffma2(e00, v01.x, o0[0]);
            o0[1] = ffma2(e00, v01.y, o0[1]);
            o0[2] = ffma2(e00, v23.x, o0[2]);
            o0[3] = ffma2(e00, v23.y, o0[3]);
            o0[4] = ffma2(e00, v45.x, o0[4]);
            o0[5] = ffma2(e00, v45.y, o0[5]);
            o0[6] = ffma2(e00, v67.x, o0[6]);
            o0[7] = ffma2(e00, v67.y, o0[7]);
        }

        if (valid)
            store_bf_split(Oh, Ol, (size_t)(o + i0) * 128 + w * 16, o0, 1.f / l0);
    }
}

// ---------------------------------------------------------------------------
extern "C" void kernel_launch(void* const* d_in, const int* in_sizes, int n_in,
                              void* d_out, int out_size)
{
    const float* att_in = (const float*)d_in[0];
    const float* in_w   = (const float*)d_in[1];
    const float* in_b   = (const float*)d_in[2];
    const float* out_w  = (const float*)d_in[3];
    const float* out_b  = (const float*)d_in[4];
    const int*   agents = (const int*)d_in[5];

    const int T = in_sizes[0] / 128;
    const int B = in_sizes[5];
    float* out  = (float*)d_out;

    float *qkv = nullptr;
    __nv_bfloat16 *oh, *ol, *wh1, *wl1, *wh2, *wl2;
    cudaGetSymbolAddress((void**)&qkv, g_qkv);
    cudaGetSymbolAddress((void**)&oh,  g_oh);
    cudaGetSymbolAddress((void**)&ol,  g_ol);
    cudaGetSymbolAddress((void**)&wh1, g_wh1);
    cudaGetSymbolAddress((void**)&wl1, g_wl1);
    cudaGetSymbolAddress((void**)&wh2, g_wh2);
    cudaGetSymbolAddress((void**)&wl2, g_wl2);

    cudaFuncSetAttribute(gemm_tc_kernel<true>,  cudaFuncAttributeMaxDynamicSharedMemorySize, GEMM_SMEM);
    cudaFuncSetAttribute(gemm_tc_kernel<false>, cudaFuncAttributeMaxDynamicSharedMemorySize, GEMM_SMEM);
    cudaFuncSetAttribute(attn_kernel, cudaFuncAttributeMaxDynamicSharedMemorySize, 65536);

    prep_kernel<<<65, 256>>>(in_w, out_w, agents, B);

    // QKV GEMM: [T x 384], A converted in-kernel
    dim3 g1(T / 64, 3);
    gemm_tc_kernel<true><<<g1, 256, GEMM_SMEM>>>(att_in, nullptr, nullptr,
                                                 wh1, wl1, in_b, qkv, 384);

    // attention -> bf16 hi/lo planes
    attn_kernel<<<B, 256, 65536>>>(qkv, oh, ol, agents, B);

    // out_proj GEMM: [T x 128], A = preconverted planes
    dim3 g2(T / 64, 1);
    gemm_tc_kernel<false><<<g2, 256, GEMM_SMEM>>>(nullptr, oh, ol,
                                                  wh2, wl2, out_b, out, 128);
}

// round 12
// speedup vs baseline: 1.1257x; 1.0232x over previous
#include <cuda_runtime.h>
#include <cuda_bf16.h>
#include <cstdint>

typedef unsigned long long ull;

#define MAXT 66560
#define MAXB 2048

// Scratch (static device allocations — no cudaMalloc allowed)
__device__ float         g_qkv[(size_t)MAXT * 384];
__device__ __nv_bfloat16 g_ah[(size_t)MAXT * 128];
__device__ __nv_bfloat16 g_al[(size_t)MAXT * 128];
__device__ __nv_bfloat16 g_oh[(size_t)MAXT * 128];
__device__ __nv_bfloat16 g_ol[(size_t)MAXT * 128];
__device__ __nv_bfloat16 g_wh1[384 * 128];
__device__ __nv_bfloat16 g_wl1[384 * 128];
__device__ __nv_bfloat16 g_wh2[128 * 128];
__device__ __nv_bfloat16 g_wl2[128 * 128];
__device__ int           g_offs[MAXB];

// ---------------------------------------------------------------------------
// f32x2 helpers
// ---------------------------------------------------------------------------
__device__ __forceinline__ ull pack2(float lo, float hi) {
    ull r;
    asm("mov.b64 %0, {%1, %2};" : "=l"(r)
        : "r"(__float_as_uint(lo)), "r"(__float_as_uint(hi)));
    return r;
}
__device__ __forceinline__ ull ffma2(ull a, ull b, ull c) {
    ull d;
    asm("fma.rn.f32x2 %0, %1, %2, %3;" : "=l"(d) : "l"(a), "l"(b), "l"(c));
    return d;
}
__device__ __forceinline__ ull mul2(ull a, ull b) {
    ull d;
    asm("mul.rn.f32x2 %0, %1, %2;" : "=l"(d) : "l"(a), "l"(b));
    return d;
}
__device__ __forceinline__ ull add2(ull a, ull b) {
    ull d;
    asm("add.rn.f32x2 %0, %1, %2;" : "=l"(d) : "l"(a), "l"(b));
    return d;
}
__device__ __forceinline__ float lo2(ull v) { return __uint_as_float((unsigned)(v & 0xffffffffull)); }
__device__ __forceinline__ float hi2(ull v) { return __uint_as_float((unsigned)(v >> 32)); }
__device__ __forceinline__ float hadd2(ull v) { return lo2(v) + hi2(v); }

__device__ __forceinline__ uint32_t smem_u32(const void* p) {
    uint32_t a;
    asm("{ .reg .u64 t; cvta.to.shared.u64 t, %1; cvt.u32.u64 %0, t; }" : "=r"(a) : "l"(p));
    return a;
}
__device__ __forceinline__ void cp16(uint32_t s, const void* g) {
    asm volatile("cp.async.ca.shared.global [%0], [%1], 16;" :: "r"(s), "l"(g));
}
#define CP_COMMIT() asm volatile("cp.async.commit_group;" ::: "memory")
#define CP_WAIT0()  asm volatile("cp.async.wait_group 0;" ::: "memory")
#define CP_WAIT1()  asm volatile("cp.async.wait_group 1;" ::: "memory")

// ---------------------------------------------------------------------------
// bf16 hi/lo split of a float4 -> two packed 8-byte values
// ---------------------------------------------------------------------------
__device__ __forceinline__ void split4(float4 v, ull& hp, ull& lp) {
    __nv_bfloat16 hx = __float2bfloat16(v.x), hy = __float2bfloat16(v.y),
                  hz = __float2bfloat16(v.z), hw = __float2bfloat16(v.w);
    hp = (ull)__bfloat16_as_ushort(hx) | ((ull)__bfloat16_as_ushort(hy) << 16)
       | ((ull)__bfloat16_as_ushort(hz) << 32) | ((ull)__bfloat16_as_ushort(hw) << 48);
    __nv_bfloat16 lx = __float2bfloat16(v.x - __bfloat162float(hx));
    __nv_bfloat16 ly = __float2bfloat16(v.y - __bfloat162float(hy));
    __nv_bfloat16 lz = __float2bfloat16(v.z - __bfloat162float(hz));
    __nv_bfloat16 lw = __float2bfloat16(v.w - __bfloat162float(hw));
    lp = (ull)__bfloat16_as_ushort(lx) | ((ull)__bfloat16_as_ushort(ly) << 16)
       | ((ull)__bfloat16_as_ushort(lz) << 32) | ((ull)__bfloat16_as_ushort(lw) << 48);
}

// ---------------------------------------------------------------------------
// Prep kernel (ONE launch):
//   blocks [0, nact)          : convert att_in fp32 -> g_ah/g_al planes
//   blocks [nact, nact+48)    : convert in_proj_w   -> g_wh1/g_wl1
//   blocks [nact+48, nact+64) : convert out_proj_w  -> g_wh2/g_wl2
//   block  nact+64            : exclusive prefix sum -> g_offs
// ---------------------------------------------------------------------------
__global__ void prep_kernel(const float* __restrict__ att_in,
                            const float* __restrict__ w1,
                            const float* __restrict__ w2,
                            const int* __restrict__ agents, int B, int T,
                            int nact)
{
    int bid = blockIdx.x;
    int tid = threadIdx.x;

    if (bid < nact) {
        int i = bid * 256 + tid;
        if (i < T * 32) {
            float4 v = ((const float4*)att_in)[i];
            ull hp, lp;
            split4(v, hp, lp);
            *(ull*)(g_ah + (size_t)i * 4) = hp;
            *(ull*)(g_al + (size_t)i * 4) = lp;
        }
        return;
    }
    int wb = bid - nact;
    if (wb < 64) {
        const float* src;
        __nv_bfloat16 *dh, *dl;
        int i;
        if (wb < 48) {
            src = w1; dh = g_wh1; dl = g_wl1;
            i = wb * 256 + tid;                 // < 12288 float4s
        } else {
            src = w2; dh = g_wh2; dl = g_wl2;
            i = (wb - 48) * 256 + tid;          // < 4096 float4s
        }
        float4 v = ((const float4*)src)[i];
        ull hp, lp;
        split4(v, hp, lp);
        *(ull*)(dh + (size_t)i * 4) = hp;
        *(ull*)(dl + (size_t)i * 4) = lp;
        return;
    }

    // ---- scan ----
    __shared__ int part[256];
    int local[8];
    int s = 0;
#pragma unroll
    for (int i = 0; i < 8; i++) {
        int idx = tid * 8 + i;
        local[i] = (idx < B) ? agents[idx] : 0;
        s += local[i];
    }
    part[tid] = s;
    __syncthreads();
    for (int d = 1; d < 256; d <<= 1) {
        int v = (tid >= d) ? part[tid - d] : 0;
        __syncthreads();
        part[tid] += v;
        __syncthreads();
    }
    int base = (tid > 0) ? part[tid - 1] : 0;
#pragma unroll
    for (int i = 0; i < 8; i++) {
        int idx = tid * 8 + i;
        if (idx < B) g_offs[idx] = base;
        base += local[i];
    }
}

// ---------------------------------------------------------------------------
// Persistent GEMM (warp HMMA): each CTA loads its 128-col W slice ONCE, then
// loops over 64-row A tiles (strided) with DOUBLE-BUFFERED cp.async fills.
// 3-term split: Ah*Wh + Ah*Wl + Al*Wh. All operands pre-converted bf16 planes.
// ---------------------------------------------------------------------------
#define ASTRIDE 136                  // bf16 elems per smem row (272B)
// smem layout (bytes):
#define SA0_H 0
#define SA0_L 17408
#define SA1_H 34816
#define SA1_L 52224
#define SW_H  69632
#define SW_L  104448
#define GEMM_SMEM 139264

__device__ __forceinline__ void ldm_x4(uint32_t* r, uint32_t addr) {
    asm volatile("ldmatrix.sync.aligned.m8n8.x4.shared.b16 {%0,%1,%2,%3}, [%4];"
                 : "=r"(r[0]), "=r"(r[1]), "=r"(r[2]), "=r"(r[3]) : "r"(addr));
}
__device__ __forceinline__ void mma_bf16(float* d, const uint32_t* a, const uint32_t* b) {
    asm volatile("mma.sync.aligned.m16n8k16.row.col.f32.bf16.bf16.f32 "
                 "{%0,%1,%2,%3}, {%4,%5,%6,%7}, {%8,%9}, {%0,%1,%2,%3};"
                 : "+f"(d[0]), "+f"(d[1]), "+f"(d[2]), "+f"(d[3])
                 : "r"(a[0]), "r"(a[1]), "r"(a[2]), "r"(a[3]), "r"(b[0]), "r"(b[1]));
}

__device__ __forceinline__ void fill_a(uint32_t sb, uint32_t off_h, uint32_t off_l,
                                       const __nv_bfloat16* Ah, const __nv_bfloat16* Al,
                                       int bm, int tid)
{
#pragma unroll
    for (int t = 0; t < 4; t++) {
        int c = tid + t * 256;           // 0..1023
        int row = c >> 4, c16 = c & 15;
        uint32_t so = (uint32_t)(row * 272 + c16 * 16);
        cp16(sb + off_h + so, (const char*)(Ah + (size_t)(bm + row) * 128) + c16 * 16);
        cp16(sb + off_l + so, (const char*)(Al + (size_t)(bm + row) * 128) + c16 * 16);
    }
}

__global__ __launch_bounds__(256) void gemm_tc_kernel(
    const __nv_bfloat16* __restrict__ Ah_g, const __nv_bfloat16* __restrict__ Al_g,
    const __nv_bfloat16* __restrict__ Wh, const __nv_bfloat16* __restrict__ Wl,
    const float* __restrict__ bias, float* __restrict__ C, int N, int ntiles)
{
    extern __shared__ char sm[];
    const uint32_t sb = smem_u32(sm);
    const int tid  = threadIdx.x;
    const int wid  = tid >> 5;
    const int lane = tid & 31;
    const int bn   = blockIdx.y * 128;
    const int t0     = blockIdx.x;
    const int stride = gridDim.x;

    // ---- W slice (128 rows, hi+lo) once ----
#pragma unroll
    for (int t = 0; t < 8; t++) {
        int c = tid + t * 256;           // 0..2047
        int row = c >> 4, c16 = c & 15;
        uint32_t so = (uint32_t)(row * 272 + c16 * 16);
        cp16(sb + SW_H + so, (const char*)(Wh + (size_t)(bn + row) * 128) + c16 * 16);
        cp16(sb + SW_L + so, (const char*)(Wl + (size_t)(bn + row) * 128) + c16 * 16);
    }
    // ---- first A tile into buffer 0 (same group as W) ----
    if (t0 < ntiles)
        fill_a(sb, SA0_H, SA0_L, Ah_g, Al_g, t0 * 64, tid);
    CP_COMMIT();

    // per-warp geometry
    const int wm = (wid & 1) * 32;
    const int wn = (wid >> 1) * 32;
    const int arow = wm + (lane & 15);
    const int acol8 = (lane >> 4) * 8;
    const int bgrp = lane >> 3;
    const int brow0 = wn + ((bgrp >> 1) << 3) + (lane & 7);
    const int bk8   = (bgrp & 1) << 3;
    const int er = lane >> 2;
    const int ec = (lane & 3) * 2;

    // bias is per-column: constant across tiles
    float bb0[4], bb1[4];
#pragma unroll
    for (int ni = 0; ni < 4; ni++) {
        int n = bn + wn + ni * 8 + ec;
        bb0[ni] = bias[n];
        bb1[ni] = bias[n + 1];
    }

    int buf = 0;
    for (int t = t0; t < ntiles; t += stride) {
        int tn = t + stride;
        if (tn < ntiles) {
            fill_a(sb, buf ? SA0_H : SA1_H, buf ? SA0_L : SA1_L,
                   Ah_g, Al_g, tn * 64, tid);
            CP_COMMIT();
            CP_WAIT1();                  // current tile (and W) resident
        } else {
            CP_WAIT0();
        }
        __syncthreads();

        const uint32_t sa_h = buf ? SA1_H : SA0_H;
        const uint32_t sa_l = buf ? SA1_L : SA0_L;

        float acc[2][4][4];
#pragma unroll
        for (int mi = 0; mi < 2; mi++)
#pragma unroll
            for (int ni = 0; ni < 4; ni++)
#pragma unroll
                for (int e = 0; e < 4; e++) acc[mi][ni][e] = 0.f;

#pragma unroll
        for (int k = 0; k < 8; k++) {
            const int kb = k * 16;
            uint32_t ahf[2][4], alf[2][4];
#pragma unroll
            for (int mi = 0; mi < 2; mi++) {
                uint32_t off = (uint32_t)(((arow + mi * 16) * ASTRIDE + kb + acol8) * 2);
                ldm_x4(ahf[mi], sb + sa_h + off);
                ldm_x4(alf[mi], sb + sa_l + off);
            }
            uint32_t bhf[4][2], blf[4][2];
#pragma unroll
            for (int nip = 0; nip < 2; nip++) {
                uint32_t off = (uint32_t)(((brow0 + nip * 16) * ASTRIDE + kb + bk8) * 2);
                ldm_x4(&bhf[nip * 2][0], sb + SW_H + off);
                ldm_x4(&blf[nip * 2][0], sb + SW_L + off);
            }
#pragma unroll
            for (int mi = 0; mi < 2; mi++)
#pragma unroll
                for (int ni = 0; ni < 4; ni++) {
                    mma_bf16(acc[mi][ni], ahf[mi], bhf[ni]);
                    mma_bf16(acc[mi][ni], ahf[mi], blf[ni]);
                    mma_bf16(acc[mi][ni], alf[mi], bhf[ni]);
                }
        }

        // ---- epilogue: bias + store tile t ----
        const int bm = t * 64;
#pragma unroll
        for (int ni = 0; ni < 4; ni++) {
            int n = bn + wn + ni * 8 + ec;
#pragma unroll
            for (int mi = 0; mi < 2; mi++) {
                int m0 = bm + wm + mi * 16 + er;
                *(float2*)(C + (size_t)m0 * N + n) =
                    make_float2(acc[mi][ni][0] + bb0[ni], acc[mi][ni][1] + bb1[ni]);
                *(float2*)(C + (size_t)(m0 + 8) * N + n) =
                    make_float2(acc[mi][ni][2] + bb0[ni], acc[mi][ni][3] + bb1[ni]);
            }
        }
        __syncthreads();
        buf ^= 1;
    }
}

// ---------------------------------------------------------------------------
// Attention (r11): block per sample, warp per head (fill K/V once, __syncwarp
// only), query halves processed sequentially. Writes bf16 hi/lo output planes.
// ---------------------------------------------------------------------------
__device__ __forceinline__ void store_bf_split(
    __nv_bfloat16* __restrict__ Oh, __nv_bfloat16* __restrict__ Ol,
    size_t base, const ull* ov, float linv)
{
    ull inv = pack2(linv, linv);
#pragma unroll
    for (int t = 0; t < 4; t++) {
        ull r0 = mul2(ov[2 * t], inv);
        ull r1 = mul2(ov[2 * t + 1], inv);
        float4 f = make_float4(lo2(r0), hi2(r0), lo2(r1), hi2(r1));
        ull hp, lp;
        split4(f, hp, lp);
        *(ull*)(Oh + base + t * 4) = hp;
        *(ull*)(Ol + base + t * 4) = lp;
    }
}

__global__ __launch_bounds__(256, 3) void attn_kernel(
    const float* __restrict__ Y,            // qkv [T][384]
    __nv_bfloat16* __restrict__ Oh,         // attn out hi plane [T][128]
    __nv_bfloat16* __restrict__ Ol,         // attn out lo plane [T][128]
    const int* __restrict__ agents, int B)
{
    extern __shared__ float smf[];       // 8 warps * (1024 K + 1024 V) floats
    // largest-first schedule (heuristic permutation; correctness reads agents[])
    int b = blockIdx.x;
    if (B == 2048) {
        int g = b >> 5, k = b & 31;
        b = (k << 6) + (63 - g);
    }
    const int n    = agents[b];
    const int o    = g_offs[b];
    const int tid  = threadIdx.x;
    const int w    = tid >> 5;           // head index
    const int lane = tid & 31;

    float* Ks = smf + w * 2048;
    float* Vs = Ks + 1024;

    int nseg = n * 4;
    for (int si = lane; si < nseg; si += 32) {
        int r = si >> 2, s = si & 3;
        const float* base = Y + (size_t)(o + r) * 384 + w * 16 + s * 4;
        *(float4*)(Ks + r * 16 + s * 4) = *(const float4*)(base + 128);
        *(float4*)(Vs + r * 16 + s * 4) = *(const float4*)(base + 256);
    }
    __syncwarp();

    const ull QSC = pack2(0.25f, 0.25f);
    const int nhalves = (n > 32) ? 2 : 1;

    for (int half = 0; half < nhalves; half++) {
        const int i0 = half * 32 + lane;
        const bool valid = i0 < n;

        ull q0[8];
#pragma unroll
        for (int d = 0; d < 8; d++) q0[d] = 0ull;
        if (valid) {
            const float4* qp = (const float4*)(Y + (size_t)(o + i0) * 384 + w * 16);
#pragma unroll
            for (int t = 0; t < 4; t++) {
                float4 v = qp[t];
                q0[t * 2 + 0] = mul2(pack2(v.x, v.y), QSC);
                q0[t * 2 + 1] = mul2(pack2(v.z, v.w), QSC);
            }
        }

        ull o0[8];
#pragma unroll
        for (int d = 0; d < 8; d++) o0[d] = 0ull;
        float l0 = 0.f;

#pragma unroll 2
        for (int j = 0; j < n; j++) {
            const ulonglong2* kp = (const ulonglong2*)(Ks + j * 16);
            ulonglong2 k01 = kp[0], k23 = kp[1], k45 = kp[2], k67 = kp[3];

            ull saA = 0, saB = 0;
            saA = ffma2(q0[0], k01.x, saA);
            saB = ffma2(q0[1], k01.y, saB);
            saA = ffma2(q0[2], k23.x, saA);
            saB = ffma2(q0[3], k23.y, saB);
            saA = ffma2(q0[4], k45.x, saA);
            saB = ffma2(q0[5], k45.y, saB);
            saA = ffma2(q0[6], k67.x, saA);
            saB = ffma2(q0[7], k67.y, saB);

            float e0 = __expf(hadd2(add2(saA, saB)));
            l0 += e0;
            ull e00 = pack2(e0, e0);

            const ulonglong2* vp = (const ulonglong2*)(Vs + j * 16);
            ulonglong2 v01 = vp[0], v23 = vp[1], v45 = vp[2], v67 = vp[3];
            o0[0] = ffma2(e00, v01.x, o0[0]);
            o0[1] = ffma2(e00, v01.y, o0[1]);
            o0[2] = ffma2(e00, v23.x, o0[2]);
            o0[3] = ffma2(e00, v23.y, o0[3]);
            o0[4] = ffma2(e00, v45.x, o0[4]);
            o0[5] = ffma2(e00, v45.y, o0[5]);
            o0[6] = ffma2(e00, v67.x, o0[6]);
            o0[7] = ffma2(e00, v67.y, o0[7]);
        }

        if (valid)
            store_bf_split(Oh, Ol, (size_t)(o + i0) * 128 + w * 16, o0, 1.f / l0);
    }
}

// ---------------------------------------------------------------------------
extern "C" void kernel_launch(void* const* d_in, const int* in_sizes, int n_in,
                              void* d_out, int out_size)
{
    const float* att_in = (const float*)d_in[0];
    const float* in_w   = (const float*)d_in[1];
    const float* in_b   = (const float*)d_in[2];
    const float* out_w  = (const float*)d_in[3];
    const float* out_b  = (const float*)d_in[4];
    const int*   agents = (const int*)d_in[5];

    const int T = in_sizes[0] / 128;
    const int B = in_sizes[5];
    float* out  = (float*)d_out;

    float *qkv = nullptr;
    __nv_bfloat16 *ah, *al, *oh, *ol, *wh1, *wl1, *wh2, *wl2;
    cudaGetSymbolAddress((void**)&qkv, g_qkv);
    cudaGetSymbolAddress((void**)&ah,  g_ah);
    cudaGetSymbolAddress((void**)&al,  g_al);
    cudaGetSymbolAddress((void**)&oh,  g_oh);
    cudaGetSymbolAddress((void**)&ol,  g_ol);
    cudaGetSymbolAddress((void**)&wh1, g_wh1);
    cudaGetSymbolAddress((void**)&wl1, g_wl1);
    cudaGetSymbolAddress((void**)&wh2, g_wh2);
    cudaGetSymbolAddress((void**)&wl2, g_wl2);

    cudaFuncSetAttribute(gemm_tc_kernel, cudaFuncAttributeMaxDynamicSharedMemorySize, GEMM_SMEM);
    cudaFuncSetAttribute(attn_kernel, cudaFuncAttributeMaxDynamicSharedMemorySize, 65536);

    // prep: activation planes + weight planes + scan (one launch)
    const int nact = (T * 32 + 255) / 256;
    prep_kernel<<<nact + 65, 256>>>(att_in, in_w, out_w, agents, B, T, nact);

    const int ntiles = T / 64;

    // QKV GEMM: persistent, one wave of 49x3 CTAs
    dim3 g1(49, 3);
    gemm_tc_kernel<<<g1, 256, GEMM_SMEM>>>(ah, al, wh1, wl1, in_b, qkv, 384, ntiles);

    // attention -> bf16 hi/lo planes
    attn_kernel<<<B, 256, 65536>>>(qkv, oh, ol, agents, B);

    // out_proj GEMM: persistent, one wave of 148 CTAs
    dim3 g2(148, 1);
    gemm_tc_kernel<<<g2, 256, GEMM_SMEM>>>(oh, ol, wh2, wl2, out_b, out, 128, ntiles);
}